// round 10
// baseline (speedup 1.0000x reference)
#include <cuda_runtime.h>
#include <cuda_bf16.h>
#include <math.h>
#include <stdint.h>

typedef __nv_bfloat16 bf16;

#define B_    16384
#define FIN_  640
#define H1_   1024
#define H2_   512
#define T1_   256
#define T2_   128
#define D_    8

#define DEVFN static __device__ __forceinline__

// ---------------- scratch (static device globals; no allocs allowed) -------
__device__ bf16 g_xb  [B_*FIN_];
__device__ bf16 g_w1t [H1_*FIN_];
__device__ bf16 g_w2t [H2_*H1_];
__device__ bf16 g_tw1t[D_*T1_*H2_];
__device__ bf16 g_tw2t[D_*T2_*T1_];
__device__ bf16 g_h1  [B_*H1_];
__device__ bf16 g_h2  [B_*H2_];
__device__ int  g_perm[B_];
__device__ int  g_counts[D_];
__device__ int  g_offs[D_];
__device__ int  g_cursor[D_];

// ---------------- helpers ---------------------------------------------------
DEVFN uint32_t smaddr(const void* p){ return (uint32_t)__cvta_generic_to_shared(p); }

DEVFN void cp16(uint32_t s, const void* g){
    asm volatile("cp.async.cg.shared.global [%0], [%1], 16;" :: "r"(s), "l"(g));
}
DEVFN void cp_commit(){ asm volatile("cp.async.commit_group;"); }

DEVFN void ldsm_x4(uint32_t* r, uint32_t addr){
    asm volatile("ldmatrix.sync.aligned.m8n8.x4.shared.b16 {%0,%1,%2,%3}, [%4];"
        : "=r"(r[0]), "=r"(r[1]), "=r"(r[2]), "=r"(r[3]) : "r"(addr));
}

DEVFN void mma16816(float* d, const uint32_t* a, const uint32_t* b){
    asm volatile(
        "mma.sync.aligned.m16n8k16.row.col.f32.bf16.bf16.f32 "
        "{%0,%1,%2,%3}, {%4,%5,%6,%7}, {%8,%9}, {%0,%1,%2,%3};\n"
        : "+f"(d[0]), "+f"(d[1]), "+f"(d[2]), "+f"(d[3])
        : "r"(a[0]), "r"(a[1]), "r"(a[2]), "r"(a[3]), "r"(b[0]), "r"(b[1]));
}

// ---------------- bucket prep: hist + scan in ONE block ---------------------
__global__ __launch_bounds__(1024,1) void bucket_prep_kernel(const int* __restrict__ dom){
    __shared__ int h[D_];
    int tid = threadIdx.x;
    if (tid < D_) h[tid] = 0;
    __syncthreads();
    int c0=0,c1=0,c2=0,c3=0,c4=0,c5=0,c6=0,c7=0;
    #pragma unroll
    for (int k=0;k<16;k++){
        int d = dom[tid + k*1024];
        c0 += (d==0); c1 += (d==1); c2 += (d==2); c3 += (d==3);
        c4 += (d==4); c5 += (d==5); c6 += (d==6); c7 += (d==7);
    }
    #pragma unroll
    for (int off=16; off; off>>=1){
        c0 += __shfl_down_sync(0xffffffffu, c0, off);
        c1 += __shfl_down_sync(0xffffffffu, c1, off);
        c2 += __shfl_down_sync(0xffffffffu, c2, off);
        c3 += __shfl_down_sync(0xffffffffu, c3, off);
        c4 += __shfl_down_sync(0xffffffffu, c4, off);
        c5 += __shfl_down_sync(0xffffffffu, c5, off);
        c6 += __shfl_down_sync(0xffffffffu, c6, off);
        c7 += __shfl_down_sync(0xffffffffu, c7, off);
    }
    if ((tid & 31) == 0){
        atomicAdd(&h[0], c0); atomicAdd(&h[1], c1);
        atomicAdd(&h[2], c2); atomicAdd(&h[3], c3);
        atomicAdd(&h[4], c4); atomicAdd(&h[5], c5);
        atomicAdd(&h[6], c6); atomicAdd(&h[7], c7);
    }
    __syncthreads();
    if (tid == 0){
        int s = 0;
        for (int d=0; d<D_; d++){
            g_offs[d] = s;
            int c = h[d];
            g_counts[d] = c;
            g_cursor[d] = 0;
            s += c;
        }
    }
}

// ---------------- mega prep: scatter + x convert + weight transposes --------
#define PREP_SCATTER  64
#define PREP_CONVX    2560
#define PREP_TILES    2432
#define PREP_BLOCKS   (PREP_SCATTER + PREP_CONVX + PREP_TILES)

DEVFN void trans_tile(const float* __restrict__ src, bf16* __restrict__ dst,
                      int K, int N, int ky, int nx, int tx, int ty,
                      float (*tile)[33]){
    int k0 = ky*32, n0 = nx*32;
    #pragma unroll
    for (int i=0;i<32;i+=8)
        tile[ty+i][tx] = src[(size_t)(k0+ty+i)*N + n0 + tx];
    __syncthreads();
    #pragma unroll
    for (int i=0;i<32;i+=8)
        dst[(size_t)(n0+ty+i)*K + k0 + tx] = __float2bfloat16(tile[tx][ty+i]);
}

__global__ __launch_bounds__(256,1) void prep_kernel(
    const int* __restrict__ dom,
    const float4* __restrict__ x4,
    const float* __restrict__ W1, const float* __restrict__ W2,
    const float* __restrict__ TW1, const float* __restrict__ TW2)
{
    __shared__ float tile[32][33];
    __shared__ int sh[D_], sbase[D_], scur[D_];
    int bid = blockIdx.x, tid = threadIdx.x;

    if (bid < PREP_SCATTER){
        if (tid < D_){ sh[tid]=0; scur[tid]=0; }
        __syncthreads();
        int i = bid*256 + tid;
        int d = dom[i];
        atomicAdd(&sh[d], 1);
        __syncthreads();
        if (tid < D_) sbase[tid] = atomicAdd(&g_cursor[tid], sh[tid]);
        __syncthreads();
        int p = atomicAdd(&scur[d], 1);
        g_perm[g_offs[d] + sbase[d] + p] = i;
        return;
    }
    if (bid < PREP_SCATTER + PREP_CONVX){
        int i0 = (bid - PREP_SCATTER)*1024 + tid;
        #pragma unroll
        for (int k=0;k<4;k++){
            int i = i0 + k*256;
            float4 v = x4[i];
            __nv_bfloat162* o = (__nv_bfloat162*)g_xb + (size_t)i*2;
            o[0] = __floats2bfloat162_rn(v.x, v.y);
            o[1] = __floats2bfloat162_rn(v.z, v.w);
        }
        return;
    }
    int t = bid - (PREP_SCATTER + PREP_CONVX);
    int tx = tid & 31, ty = tid >> 5;
    if (t < 640){
        trans_tile(W1, g_w1t, FIN_, H1_, t/32, t%32, tx, ty, tile);
    } else if (t < 1152){
        int t2 = t - 640;
        trans_tile(W2, g_w2t, H1_, H2_, t2/16, t2%16, tx, ty, tile);
    } else if (t < 2176){
        int t3 = t - 1152;
        int z = t3 >> 7, r = t3 & 127;
        trans_tile(TW1 + (size_t)z*H2_*T1_, g_tw1t + (size_t)z*T1_*H2_,
                   H2_, T1_, r/8, r%8, tx, ty, tile);
    } else {
        int t4 = t - 2176;
        int z = t4 >> 5, r = t4 & 31;
        trans_tile(TW2 + (size_t)z*T1_*T2_, g_tw2t + (size_t)z*T2_*T1_,
                   T1_, T2_, r/4, r%4, tx, ty, tile);
    }
}

// ---------------- HMMA GEMM (R5 proven config): 128x128, 2 CTAs/SM ---------
__global__ __launch_bounds__(256,2) void gemm_bf16_kernel(
    const bf16* __restrict__ A,
    const bf16* __restrict__ Bt,
    const float* __restrict__ bias,
    bf16* __restrict__ Cout,
    int M, int N, int K)
{
    constexpr int BM=128, BN=128, BK=64, LDS=BK+8;
    constexpr int STG = BM*LDS;
    extern __shared__ bf16 sm[];
    bf16* As = sm;
    bf16* Bs = sm + 2*STG;

    int tid = threadIdx.x;
    int m0 = blockIdx.x*BM;
    int n0 = blockIdx.y*BN;

    auto load_tile = [&](int st, int kt){
        int k0 = kt*BK;
        #pragma unroll
        for (int i=0;i<4;i++){
            int v = tid + 256*i;
            int r = v>>3, c = v&7;
            cp16(smaddr(&As[st*STG + r*LDS + c*8]), A + (size_t)(m0 + r)*K + k0 + c*8);
        }
        #pragma unroll
        for (int i=0;i<4;i++){
            int v = tid + 256*i;
            int r = v>>3, c = v&7;
            cp16(smaddr(&Bs[st*STG + r*LDS + c*8]), Bt + (size_t)(n0 + r)*K + k0 + c*8);
        }
    };

    int warp = tid>>5, lane = tid&31;
    int wm = warp & 3, wn = warp >> 2;     // 4 x 2
    int g  = lane>>2,  tg = lane&3;

    int a_row = wm*32 + (lane&7) + ((lane&8)?8:0);
    int a_ko  = (lane&16)?8:0;
    int b_row = wn*64 + (lane&7) + ((lane&16)?8:0);
    int b_ko  = (lane&8)?8:0;

    float acc[2][8][4];
    #pragma unroll
    for (int a=0;a<2;a++)
        #pragma unroll
        for (int b=0;b<8;b++)
            #pragma unroll
            for (int c=0;c<4;c++) acc[a][b][c]=0.f;

    const int KT = K/BK;
    load_tile(0, 0); cp_commit();
    for (int kt=0; kt<KT; kt++){
        if (kt+1 < KT){
            load_tile((kt+1)&1, kt+1); cp_commit();
            asm volatile("cp.async.wait_group 1;");
        } else {
            asm volatile("cp.async.wait_group 0;");
        }
        __syncthreads();
        uint32_t asb = smaddr(&As[(kt&1)*STG]);
        uint32_t bsb = smaddr(&Bs[(kt&1)*STG]);
        #pragma unroll
        for (int kk=0; kk<4; kk++){
            uint32_t af[2][4];
            #pragma unroll
            for (int mt=0; mt<2; mt++)
                ldsm_x4(af[mt], asb + (uint32_t)(((a_row + mt*16)*LDS) + kk*16 + a_ko)*2u);
            #pragma unroll
            for (int ntp=0; ntp<4; ntp++){
                uint32_t bf[4];
                ldsm_x4(bf, bsb + (uint32_t)(((b_row + ntp*16)*LDS) + kk*16 + b_ko)*2u);
                #pragma unroll
                for (int mt=0; mt<2; mt++){
                    mma16816(acc[mt][2*ntp],   af[mt], bf);
                    mma16816(acc[mt][2*ntp+1], af[mt], bf+2);
                }
            }
        }
        __syncthreads();
    }

    #pragma unroll
    for (int nt=0; nt<8; nt++){
        int c = n0 + wn*64 + nt*8 + tg*2;
        float bv0 = bias[c], bv1 = bias[c+1];
        #pragma unroll
        for (int mt=0; mt<2; mt++){
            int rl0 = wm*32 + mt*16 + g;
            int rl1 = rl0 + 8;
            float v00 = fmaxf(acc[mt][nt][0] + bv0, 0.f);
            float v01 = fmaxf(acc[mt][nt][1] + bv1, 0.f);
            float v10 = fmaxf(acc[mt][nt][2] + bv0, 0.f);
            float v11 = fmaxf(acc[mt][nt][3] + bv1, 0.f);
            *(__nv_bfloat162*)&Cout[(size_t)(m0+rl0)*N + c] = __floats2bfloat162_rn(v00, v01);
            *(__nv_bfloat162*)&Cout[(size_t)(m0+rl1)*N + c] = __floats2bfloat162_rn(v10, v11);
        }
    }
}

// ---------------- FUSED tower v2: BM=64, single-pass N, 2 CTAs/SM ----------
// Per (m-block of 64, domain) CTA:
//   phase1: t1[64x256] = relu(h2[perm rows] @ TW1[d]^T + Tb1[d]) -> smem
//   phase2: t2 = relu(t1 @ TW2[d]^T + Tb2[d]); logit = t2.TWo[d]+Tbo; out.
// 256 threads. Phase1: warps 2(M)x4(N), warp 32x64. Phase2: 2(M)x4(N), 32x32.
#define TW_BM      64
#define TW_LDS1    40                     /* pipeline padded halves per row */
#define TW_PIPE_H  (2*(TW_BM + T1_)*TW_LDS1)   /* 2 stages A(64)+B(256): 25600 halves */
#define TW_T1_LDS  264
#define TW_SMEM    ((TW_PIPE_H + TW_BM*TW_T1_LDS) * 2)   /* 51200 + 33792 = 84992 B */

__global__ __launch_bounds__(256,2) void tower_kernel(
    const float* __restrict__ Tb1,   // [D][256]
    const float* __restrict__ Tb2,   // [D][128]
    const float* __restrict__ TWo,   // [D][128]
    const float* __restrict__ Tbo,   // [D][1]
    float* __restrict__ out)
{
    constexpr int BK=32;
    constexpr int ASTG = TW_BM*TW_LDS1;      // 2560 halves
    constexpr int BSTG = T1_*TW_LDS1;        // 10240 halves
    extern __shared__ bf16 sm[];
    bf16* As  = sm;                          // phase1 A stages (2)
    bf16* Bs  = sm + 2*ASTG;                 // phase1 B stages (2)
    bf16* Bs2 = sm;                          // phase2 B stages (reuse; 2x128x40)
    bf16* t1s = sm + TW_PIPE_H;              // t1 [64][264]
    __shared__ int s_rows[TW_BM];
    __shared__ float srow[TW_BM];

    int tid = threadIdx.x;
    int d = blockIdx.y;
    int cnt = g_counts[d];
    int m0 = blockIdx.x*TW_BM;
    if (m0 >= cnt) return;
    int rbase = g_offs[d] + m0;
    int limit = min(TW_BM, cnt - m0);
    if (tid < TW_BM){
        s_rows[tid] = (tid < limit) ? g_perm[rbase + tid] : g_perm[rbase];
        srow[tid] = 0.f;
    }
    __syncthreads();

    const bf16* Bt1 = g_tw1t + (size_t)d*T1_*H2_;   // [256][512]
    const bf16* Bt2 = g_tw2t + (size_t)d*T2_*T1_;   // [128][256]
    const float* tb1 = Tb1 + d*T1_;
    const float* tb2 = Tb2 + d*T2_;
    const float* wo  = TWo + d*T2_;

    int warp = tid>>5, lane = tid&31;
    int wm = warp & 1, wn = warp >> 1;     // 2 x 4
    int g  = lane>>2,  tg = lane&3;

    int a_row = wm*32 + (lane&7) + ((lane&8)?8:0);
    int a_ko  = (lane&16)?8:0;
    int b_row = wn*64 + (lane&7) + ((lane&16)?8:0);    // phase1: 4 warps x 64 n
    int b_ko  = (lane&8)?8:0;

    float acc[2][8][4];
    #pragma unroll
    for (int a=0;a<2;a++)
        #pragma unroll
        for (int b=0;b<8;b++)
            #pragma unroll
            for (int c=0;c<4;c++) acc[a][b][c]=0.f;

    // ================= phase 1: t1 = relu(h2 @ TW1^T + Tb1), one pass =======
    auto load1 = [&](int st, int kt){
        int k0 = kt*BK;
        {   // A: 64 rows x 4 chunks of 16B
            int r = tid>>2, c = tid&3;
            cp16(smaddr(&As[st*ASTG + r*TW_LDS1 + c*8]), g_h2 + (size_t)s_rows[r]*H2_ + k0 + c*8);
        }
        #pragma unroll
        for (int i=0;i<4;i++){  // B: 256 rows x 4 chunks
            int v = tid + 256*i;
            int r = v>>2, c = v&3;
            cp16(smaddr(&Bs[st*BSTG + r*TW_LDS1 + c*8]), Bt1 + (size_t)r*H2_ + k0 + c*8);
        }
    };

    {
        constexpr int KT = H2_/BK;   // 16
        load1(0, 0); cp_commit();
        for (int kt=0; kt<KT; kt++){
            if (kt+1 < KT){
                load1((kt+1)&1, kt+1); cp_commit();
                asm volatile("cp.async.wait_group 1;");
            } else {
                asm volatile("cp.async.wait_group 0;");
            }
            __syncthreads();
            uint32_t asb = smaddr(&As[(kt&1)*ASTG]);
            uint32_t bsb = smaddr(&Bs[(kt&1)*BSTG]);
            #pragma unroll
            for (int kk=0; kk<2; kk++){
                uint32_t af[2][4];
                #pragma unroll
                for (int mt=0; mt<2; mt++)
                    ldsm_x4(af[mt], asb + (uint32_t)(((a_row + mt*16)*TW_LDS1) + kk*16 + a_ko)*2u);
                #pragma unroll
                for (int ntp=0; ntp<4; ntp++){
                    uint32_t bf[4];
                    ldsm_x4(bf, bsb + (uint32_t)(((b_row + ntp*16)*TW_LDS1) + kk*16 + b_ko)*2u);
                    #pragma unroll
                    for (int mt=0; mt<2; mt++){
                        mma16816(acc[mt][2*ntp],   af[mt], bf);
                        mma16816(acc[mt][2*ntp+1], af[mt], bf+2);
                    }
                }
            }
            __syncthreads();
        }
    }

    // write t1 -> smem (bias + relu)
    #pragma unroll
    for (int nt=0; nt<8; nt++){
        int c = wn*64 + nt*8 + tg*2;
        float bv0 = tb1[c], bv1 = tb1[c+1];
        #pragma unroll
        for (int mt=0; mt<2; mt++){
            int rl0 = wm*32 + mt*16 + g;
            int rl1 = rl0 + 8;
            float v00 = fmaxf(acc[mt][nt][0] + bv0, 0.f);
            float v01 = fmaxf(acc[mt][nt][1] + bv1, 0.f);
            float v10 = fmaxf(acc[mt][nt][2] + bv0, 0.f);
            float v11 = fmaxf(acc[mt][nt][3] + bv1, 0.f);
            *(__nv_bfloat162*)&t1s[rl0*TW_T1_LDS + c] = __floats2bfloat162_rn(v00, v01);
            *(__nv_bfloat162*)&t1s[rl1*TW_T1_LDS + c] = __floats2bfloat162_rn(v10, v11);
        }
    }
    __syncthreads();   // t1 complete; pipeline region free for phase2 B

    // ================= phase 2: t2 = relu(t1 @ TW2^T + Tb2) =================
    // warps 2(M) x 4(N of 32); acc2[2][4][4]
    int b2_row = wn*32 + (lane&7) + ((lane&16)?8:0);
    float acc2[2][4][4];
    #pragma unroll
    for (int a=0;a<2;a++)
        #pragma unroll
        for (int b=0;b<4;b++)
            #pragma unroll
            for (int c=0;c<4;c++) acc2[a][b][c]=0.f;

    auto load2 = [&](int st, int kt){
        int k0 = kt*BK;
        #pragma unroll
        for (int i=0;i<2;i++){  // 128 rows x 4 chunks
            int v = tid + 256*i;
            int r = v>>2, c = v&3;
            cp16(smaddr(&Bs2[st*(T2_*TW_LDS1) + r*TW_LDS1 + c*8]), Bt2 + (size_t)r*T1_ + k0 + c*8);
        }
    };

    {
        constexpr int KT2 = T1_/BK;   // 8
        uint32_t t1b = smaddr(t1s);
        load2(0, 0); cp_commit();
        for (int kt=0; kt<KT2; kt++){
            if (kt+1 < KT2){
                load2((kt+1)&1, kt+1); cp_commit();
                asm volatile("cp.async.wait_group 1;");
            } else {
                asm volatile("cp.async.wait_group 0;");
            }
            __syncthreads();
            uint32_t bsb = smaddr(&Bs2[(kt&1)*(T2_*TW_LDS1)]);
            #pragma unroll
            for (int kk=0; kk<2; kk++){
                uint32_t af[2][4];
                #pragma unroll
                for (int mt=0; mt<2; mt++)
                    ldsm_x4(af[mt], t1b + (uint32_t)(((a_row + mt*16)*TW_T1_LDS) + kt*32 + kk*16 + a_ko)*2u);
                #pragma unroll
                for (int ntp=0; ntp<2; ntp++){
                    uint32_t bf[4];
                    ldsm_x4(bf, bsb + (uint32_t)(((b2_row + ntp*16)*TW_LDS1) + kk*16 + b_ko)*2u);
                    #pragma unroll
                    for (int mt=0; mt<2; mt++){
                        mma16816(acc2[mt][2*ntp],   af[mt], bf);
                        mma16816(acc2[mt][2*ntp+1], af[mt], bf+2);
                    }
                }
            }
            __syncthreads();
        }
    }

    // ================= logit + sigmoid + scatter ============================
    #pragma unroll
    for (int mt=0; mt<2; mt++){
        float s0 = 0.f, s1 = 0.f;
        #pragma unroll
        for (int nt=0; nt<4; nt++){
            int c = wn*32 + nt*8 + tg*2;
            float b0 = tb2[c], b1 = tb2[c+1];
            float w0 = wo[c],  w1 = wo[c+1];
            s0 += fmaxf(acc2[mt][nt][0] + b0, 0.f)*w0 + fmaxf(acc2[mt][nt][1] + b1, 0.f)*w1;
            s1 += fmaxf(acc2[mt][nt][2] + b0, 0.f)*w0 + fmaxf(acc2[mt][nt][3] + b1, 0.f)*w1;
        }
        s0 += __shfl_xor_sync(0xffffffffu, s0, 1);
        s0 += __shfl_xor_sync(0xffffffffu, s0, 2);
        s1 += __shfl_xor_sync(0xffffffffu, s1, 1);
        s1 += __shfl_xor_sync(0xffffffffu, s1, 2);
        if (tg == 0){
            int r = wm*32 + mt*16 + g;
            atomicAdd(&srow[r],     s0);
            atomicAdd(&srow[r + 8], s1);
        }
    }
    __syncthreads();

    if (tid < limit){
        float logit = srow[tid] + Tbo[d];
        out[g_perm[rbase + tid]] = 1.f / (1.f + expf(-logit));
    }
}

// ---------------- launch ----------------------------------------------------
extern "C" void kernel_launch(void* const* d_in, const int* in_sizes, int n_in,
                              void* d_out, int out_size)
{
    const float* x    = (const float*)d_in[0];
    const int*   dom  = (const int*)  d_in[1];
    const float* W1   = (const float*)d_in[2];
    const float* b1   = (const float*)d_in[3];
    const float* W2   = (const float*)d_in[4];
    const float* b2   = (const float*)d_in[5];
    const float* TW1  = (const float*)d_in[6];
    const float* Tb1  = (const float*)d_in[7];
    const float* TW2  = (const float*)d_in[8];
    const float* Tb2  = (const float*)d_in[9];
    const float* TWo  = (const float*)d_in[10];
    const float* Tbo  = (const float*)d_in[11];
    float* out = (float*)d_out;

    void *p;
    cudaGetSymbolAddress(&p, g_xb);   bf16* xb   = (bf16*)p;
    cudaGetSymbolAddress(&p, g_w1t);  bf16* w1t  = (bf16*)p;
    cudaGetSymbolAddress(&p, g_w2t);  bf16* w2t  = (bf16*)p;
    cudaGetSymbolAddress(&p, g_h1);   bf16* h1   = (bf16*)p;
    cudaGetSymbolAddress(&p, g_h2);   bf16* h2   = (bf16*)p;

    const int GEMM_SMEM = (2*128*72 + 2*128*72) * (int)sizeof(bf16);  // 73728
    cudaFuncSetAttribute(gemm_bf16_kernel, cudaFuncAttributeMaxDynamicSharedMemorySize, GEMM_SMEM);
    cudaFuncSetAttribute(tower_kernel,     cudaFuncAttributeMaxDynamicSharedMemorySize, TW_SMEM);

    // 1) bucket hist+scan (single block)
    bucket_prep_kernel<<<1, 1024>>>(dom);

    // 2) mega prep: scatter + x convert + all weight transposes
    prep_kernel<<<PREP_BLOCKS, 256>>>(dom, (const float4*)x, W1, W2, TW1, TW2);

    // 3) bottom MLP
    gemm_bf16_kernel<<<dim3(B_/128, H1_/128), 256, GEMM_SMEM>>>(
        xb, w1t, b1, h1, B_, H1_, FIN_);
    gemm_bf16_kernel<<<dim3(B_/128, H2_/128), 256, GEMM_SMEM>>>(
        h1, w2t, b2, h2, B_, H2_, H1_);

    // 4) fused towers: L1+L2+L3 + sigmoid + scatter (BM=64, 2 CTAs/SM)
    tower_kernel<<<dim3(B_/TW_BM, D_), 256, TW_SMEM>>>(Tb1, Tb2, TWo, Tbo, out);
}

// round 11
// speedup vs baseline: 1.0333x; 1.0333x over previous
#include <cuda_runtime.h>
#include <cuda_bf16.h>
#include <math.h>
#include <stdint.h>

typedef __nv_bfloat16 bf16;

#define B_    16384
#define FIN_  640
#define H1_   1024
#define H2_   512
#define T1_   256
#define T2_   128
#define D_    8

#define DEVFN static __device__ __forceinline__

// ---------------- scratch (static device globals; no allocs allowed) -------
__device__ bf16 g_xb  [B_*FIN_];
__device__ bf16 g_w1t [H1_*FIN_];
__device__ bf16 g_w2t [H2_*H1_];
__device__ bf16 g_tw1t[D_*T1_*H2_];
__device__ bf16 g_tw2t[D_*T2_*T1_];
__device__ bf16 g_h1  [B_*H1_];
__device__ bf16 g_h2  [B_*H2_];
__device__ int  g_perm[D_*B_];      // fixed-stride buckets: domain d at d*B_
__device__ int  g_counts[D_];
__device__ int  g_cursor[D_];       // zeroed by GEMM1 fixup each call

// ---------------- helpers ---------------------------------------------------
DEVFN uint32_t smaddr(const void* p){ return (uint32_t)__cvta_generic_to_shared(p); }

DEVFN void cp16(uint32_t s, const void* g){
    asm volatile("cp.async.cg.shared.global [%0], [%1], 16;" :: "r"(s), "l"(g));
}
DEVFN void cp_commit(){ asm volatile("cp.async.commit_group;"); }

DEVFN void ldsm_x4(uint32_t* r, uint32_t addr){
    asm volatile("ldmatrix.sync.aligned.m8n8.x4.shared.b16 {%0,%1,%2,%3}, [%4];"
        : "=r"(r[0]), "=r"(r[1]), "=r"(r[2]), "=r"(r[3]) : "r"(addr));
}

DEVFN void mma16816(float* d, const uint32_t* a, const uint32_t* b){
    asm volatile(
        "mma.sync.aligned.m16n8k16.row.col.f32.bf16.bf16.f32 "
        "{%0,%1,%2,%3}, {%4,%5,%6,%7}, {%8,%9}, {%0,%1,%2,%3};\n"
        : "+f"(d[0]), "+f"(d[1]), "+f"(d[2]), "+f"(d[3])
        : "r"(a[0]), "r"(a[1]), "r"(a[2]), "r"(a[3]), "r"(b[0]), "r"(b[1]));
}

// ---------------- mega prep: scatter + x convert + weight transposes --------
#define PREP_SCATTER  64
#define PREP_CONVX    2560
#define PREP_TILES    2432
#define PREP_BLOCKS   (PREP_SCATTER + PREP_CONVX + PREP_TILES)

DEVFN void trans_tile(const float* __restrict__ src, bf16* __restrict__ dst,
                      int K, int N, int ky, int nx, int tx, int ty,
                      float (*tile)[33]){
    int k0 = ky*32, n0 = nx*32;
    #pragma unroll
    for (int i=0;i<32;i+=8)
        tile[ty+i][tx] = src[(size_t)(k0+ty+i)*N + n0 + tx];
    __syncthreads();
    #pragma unroll
    for (int i=0;i<32;i+=8)
        dst[(size_t)(n0+ty+i)*K + k0 + tx] = __float2bfloat16(tile[tx][ty+i]);
}

__global__ __launch_bounds__(256,1) void prep_kernel(
    const int* __restrict__ dom,
    const float4* __restrict__ x4,
    const float* __restrict__ W1, const float* __restrict__ W2,
    const float* __restrict__ TW1, const float* __restrict__ TW2)
{
    __shared__ float tile[32][33];
    __shared__ int sh[D_], sbase[D_], scur[D_];
    int bid = blockIdx.x, tid = threadIdx.x;

    if (bid < PREP_SCATTER){
        // scatter into fixed-stride buckets; no global prefix scan needed
        if (tid < D_){ sh[tid]=0; scur[tid]=0; }
        __syncthreads();
        int i = bid*256 + tid;
        int d = dom[i];
        atomicAdd(&sh[d], 1);
        __syncthreads();
        if (tid < D_ && sh[tid] > 0)
            sbase[tid] = atomicAdd(&g_cursor[tid], sh[tid]);
        __syncthreads();
        int p = atomicAdd(&scur[d], 1);
        g_perm[d*B_ + sbase[d] + p] = i;
        return;
    }
    if (bid < PREP_SCATTER + PREP_CONVX){
        int i0 = (bid - PREP_SCATTER)*1024 + tid;
        #pragma unroll
        for (int k=0;k<4;k++){
            int i = i0 + k*256;
            float4 v = x4[i];
            __nv_bfloat162* o = (__nv_bfloat162*)g_xb + (size_t)i*2;
            o[0] = __floats2bfloat162_rn(v.x, v.y);
            o[1] = __floats2bfloat162_rn(v.z, v.w);
        }
        return;
    }
    int t = bid - (PREP_SCATTER + PREP_CONVX);
    int tx = tid & 31, ty = tid >> 5;
    if (t < 640){
        trans_tile(W1, g_w1t, FIN_, H1_, t/32, t%32, tx, ty, tile);
    } else if (t < 1152){
        int t2 = t - 640;
        trans_tile(W2, g_w2t, H1_, H2_, t2/16, t2%16, tx, ty, tile);
    } else if (t < 2176){
        int t3 = t - 1152;
        int z = t3 >> 7, r = t3 & 127;
        trans_tile(TW1 + (size_t)z*H2_*T1_, g_tw1t + (size_t)z*T1_*H2_,
                   H2_, T1_, r/8, r%8, tx, ty, tile);
    } else {
        int t4 = t - 2176;
        int z = t4 >> 5, r = t4 & 31;
        trans_tile(TW2 + (size_t)z*T1_*T2_, g_tw2t + (size_t)z*T2_*T1_,
                   T1_, T2_, r/4, r%4, tx, ty, tile);
    }
}

// ---------------- HMMA GEMM (proven config): 128x128, 2 CTAs/SM ------------
// FIXUP: block(0,0) thread0 snapshots cursor->counts and zeroes cursor
// (runs between prep and tower in stream order; kernel boundary = ordering).
template<bool FIXUP>
__global__ __launch_bounds__(256,2) void gemm_bf16_kernel(
    const bf16* __restrict__ A,
    const bf16* __restrict__ Bt,
    const float* __restrict__ bias,
    bf16* __restrict__ Cout,
    int M, int N, int K)
{
    constexpr int BM=128, BN=128, BK=64, LDS=BK+8;
    constexpr int STG = BM*LDS;
    extern __shared__ bf16 sm[];
    bf16* As = sm;
    bf16* Bs = sm + 2*STG;

    int tid = threadIdx.x;
    if (FIXUP && blockIdx.x==0 && blockIdx.y==0 && tid==0){
        #pragma unroll
        for (int d=0; d<D_; d++){
            g_counts[d] = g_cursor[d];
            g_cursor[d] = 0;
        }
    }

    int m0 = blockIdx.x*BM;
    int n0 = blockIdx.y*BN;

    auto load_tile = [&](int st, int kt){
        int k0 = kt*BK;
        #pragma unroll
        for (int i=0;i<4;i++){
            int v = tid + 256*i;
            int r = v>>3, c = v&7;
            cp16(smaddr(&As[st*STG + r*LDS + c*8]), A + (size_t)(m0 + r)*K + k0 + c*8);
        }
        #pragma unroll
        for (int i=0;i<4;i++){
            int v = tid + 256*i;
            int r = v>>3, c = v&7;
            cp16(smaddr(&Bs[st*STG + r*LDS + c*8]), Bt + (size_t)(n0 + r)*K + k0 + c*8);
        }
    };

    int warp = tid>>5, lane = tid&31;
    int wm = warp & 3, wn = warp >> 2;     // 4 x 2
    int g  = lane>>2,  tg = lane&3;

    int a_row = wm*32 + (lane&7) + ((lane&8)?8:0);
    int a_ko  = (lane&16)?8:0;
    int b_row = wn*64 + (lane&7) + ((lane&16)?8:0);
    int b_ko  = (lane&8)?8:0;

    float acc[2][8][4];
    #pragma unroll
    for (int a=0;a<2;a++)
        #pragma unroll
        for (int b=0;b<8;b++)
            #pragma unroll
            for (int c=0;c<4;c++) acc[a][b][c]=0.f;

    const int KT = K/BK;
    load_tile(0, 0); cp_commit();
    for (int kt=0; kt<KT; kt++){
        if (kt+1 < KT){
            load_tile((kt+1)&1, kt+1); cp_commit();
            asm volatile("cp.async.wait_group 1;");
        } else {
            asm volatile("cp.async.wait_group 0;");
        }
        __syncthreads();
        uint32_t asb = smaddr(&As[(kt&1)*STG]);
        uint32_t bsb = smaddr(&Bs[(kt&1)*STG]);
        #pragma unroll
        for (int kk=0; kk<4; kk++){
            uint32_t af[2][4];
            #pragma unroll
            for (int mt=0; mt<2; mt++)
                ldsm_x4(af[mt], asb + (uint32_t)(((a_row + mt*16)*LDS) + kk*16 + a_ko)*2u);
            #pragma unroll
            for (int ntp=0; ntp<4; ntp++){
                uint32_t bf[4];
                ldsm_x4(bf, bsb + (uint32_t)(((b_row + ntp*16)*LDS) + kk*16 + b_ko)*2u);
                #pragma unroll
                for (int mt=0; mt<2; mt++){
                    mma16816(acc[mt][2*ntp],   af[mt], bf);
                    mma16816(acc[mt][2*ntp+1], af[mt], bf+2);
                }
            }
        }
        __syncthreads();
    }

    #pragma unroll
    for (int nt=0; nt<8; nt++){
        int c = n0 + wn*64 + nt*8 + tg*2;
        float bv0 = bias[c], bv1 = bias[c+1];
        #pragma unroll
        for (int mt=0; mt<2; mt++){
            int rl0 = wm*32 + mt*16 + g;
            int rl1 = rl0 + 8;
            float v00 = fmaxf(acc[mt][nt][0] + bv0, 0.f);
            float v01 = fmaxf(acc[mt][nt][1] + bv1, 0.f);
            float v10 = fmaxf(acc[mt][nt][2] + bv0, 0.f);
            float v11 = fmaxf(acc[mt][nt][3] + bv1, 0.f);
            *(__nv_bfloat162*)&Cout[(size_t)(m0+rl0)*N + c] = __floats2bfloat162_rn(v00, v01);
            *(__nv_bfloat162*)&Cout[(size_t)(m0+rl1)*N + c] = __floats2bfloat162_rn(v10, v11);
        }
    }
}

// ---------------- FUSED tower: BM=64, single-pass N, 2 CTAs/SM -------------
#define TW_BM      64
#define TW_LDS1    40
#define TW_PIPE_H  (2*(TW_BM + T1_)*TW_LDS1)
#define TW_T1_LDS  264
#define TW_SMEM    ((TW_PIPE_H + TW_BM*TW_T1_LDS) * 2)

__global__ __launch_bounds__(256,2) void tower_kernel(
    const float* __restrict__ Tb1,
    const float* __restrict__ Tb2,
    const float* __restrict__ TWo,
    const float* __restrict__ Tbo,
    float* __restrict__ out)
{
    constexpr int BK=32;
    constexpr int ASTG = TW_BM*TW_LDS1;
    constexpr int BSTG = T1_*TW_LDS1;
    extern __shared__ bf16 sm[];
    bf16* As  = sm;
    bf16* Bs  = sm + 2*ASTG;
    bf16* Bs2 = sm;
    bf16* t1s = sm + TW_PIPE_H;
    __shared__ int s_rows[TW_BM];
    __shared__ float srow[TW_BM];

    int tid = threadIdx.x;
    int d = blockIdx.y;
    int cnt = g_counts[d];
    int m0 = blockIdx.x*TW_BM;
    if (m0 >= cnt) return;
    const int* permd = g_perm + d*B_;
    int limit = min(TW_BM, cnt - m0);
    if (tid < TW_BM){
        s_rows[tid] = (tid < limit) ? permd[m0 + tid] : permd[m0];
        srow[tid] = 0.f;
    }
    __syncthreads();

    const bf16* Bt1 = g_tw1t + (size_t)d*T1_*H2_;
    const bf16* Bt2 = g_tw2t + (size_t)d*T2_*T1_;
    const float* tb1 = Tb1 + d*T1_;
    const float* tb2 = Tb2 + d*T2_;
    const float* wo  = TWo + d*T2_;

    int warp = tid>>5, lane = tid&31;
    int wm = warp & 1, wn = warp >> 1;     // 2 x 4
    int g  = lane>>2,  tg = lane&3;

    int a_row = wm*32 + (lane&7) + ((lane&8)?8:0);
    int a_ko  = (lane&16)?8:0;
    int b_row = wn*64 + (lane&7) + ((lane&16)?8:0);
    int b_ko  = (lane&8)?8:0;

    float acc[2][8][4];
    #pragma unroll
    for (int a=0;a<2;a++)
        #pragma unroll
        for (int b=0;b<8;b++)
            #pragma unroll
            for (int c=0;c<4;c++) acc[a][b][c]=0.f;

    // phase 1: t1 = relu(h2 @ TW1^T + Tb1), single pass over N=256
    auto load1 = [&](int st, int kt){
        int k0 = kt*BK;
        {
            int r = tid>>2, c = tid&3;
            cp16(smaddr(&As[st*ASTG + r*TW_LDS1 + c*8]), g_h2 + (size_t)s_rows[r]*H2_ + k0 + c*8);
        }
        #pragma unroll
        for (int i=0;i<4;i++){
            int v = tid + 256*i;
            int r = v>>2, c = v&3;
            cp16(smaddr(&Bs[st*BSTG + r*TW_LDS1 + c*8]), Bt1 + (size_t)r*H2_ + k0 + c*8);
        }
    };

    {
        constexpr int KT = H2_/BK;   // 16
        load1(0, 0); cp_commit();
        for (int kt=0; kt<KT; kt++){
            if (kt+1 < KT){
                load1((kt+1)&1, kt+1); cp_commit();
                asm volatile("cp.async.wait_group 1;");
            } else {
                asm volatile("cp.async.wait_group 0;");
            }
            __syncthreads();
            uint32_t asb = smaddr(&As[(kt&1)*ASTG]);
            uint32_t bsb = smaddr(&Bs[(kt&1)*BSTG]);
            #pragma unroll
            for (int kk=0; kk<2; kk++){
                uint32_t af[2][4];
                #pragma unroll
                for (int mt=0; mt<2; mt++)
                    ldsm_x4(af[mt], asb + (uint32_t)(((a_row + mt*16)*TW_LDS1) + kk*16 + a_ko)*2u);
                #pragma unroll
                for (int ntp=0; ntp<4; ntp++){
                    uint32_t bf[4];
                    ldsm_x4(bf, bsb + (uint32_t)(((b_row + ntp*16)*TW_LDS1) + kk*16 + b_ko)*2u);
                    #pragma unroll
                    for (int mt=0; mt<2; mt++){
                        mma16816(acc[mt][2*ntp],   af[mt], bf);
                        mma16816(acc[mt][2*ntp+1], af[mt], bf+2);
                    }
                }
            }
            __syncthreads();
        }
    }

    #pragma unroll
    for (int nt=0; nt<8; nt++){
        int c = wn*64 + nt*8 + tg*2;
        float bv0 = tb1[c], bv1 = tb1[c+1];
        #pragma unroll
        for (int mt=0; mt<2; mt++){
            int rl0 = wm*32 + mt*16 + g;
            int rl1 = rl0 + 8;
            float v00 = fmaxf(acc[mt][nt][0] + bv0, 0.f);
            float v01 = fmaxf(acc[mt][nt][1] + bv1, 0.f);
            float v10 = fmaxf(acc[mt][nt][2] + bv0, 0.f);
            float v11 = fmaxf(acc[mt][nt][3] + bv1, 0.f);
            *(__nv_bfloat162*)&t1s[rl0*TW_T1_LDS + c] = __floats2bfloat162_rn(v00, v01);
            *(__nv_bfloat162*)&t1s[rl1*TW_T1_LDS + c] = __floats2bfloat162_rn(v10, v11);
        }
    }
    __syncthreads();

    // phase 2: t2 = relu(t1 @ TW2^T + Tb2)
    int b2_row = wn*32 + (lane&7) + ((lane&16)?8:0);
    float acc2[2][4][4];
    #pragma unroll
    for (int a=0;a<2;a++)
        #pragma unroll
        for (int b=0;b<4;b++)
            #pragma unroll
            for (int c=0;c<4;c++) acc2[a][b][c]=0.f;

    auto load2 = [&](int st, int kt){
        int k0 = kt*BK;
        #pragma unroll
        for (int i=0;i<2;i++){
            int v = tid + 256*i;
            int r = v>>2, c = v&3;
            cp16(smaddr(&Bs2[st*(T2_*TW_LDS1) + r*TW_LDS1 + c*8]), Bt2 + (size_t)r*T1_ + k0 + c*8);
        }
    };

    {
        constexpr int KT2 = T1_/BK;   // 8
        uint32_t t1b = smaddr(t1s);
        load2(0, 0); cp_commit();
        for (int kt=0; kt<KT2; kt++){
            if (kt+1 < KT2){
                load2((kt+1)&1, kt+1); cp_commit();
                asm volatile("cp.async.wait_group 1;");
            } else {
                asm volatile("cp.async.wait_group 0;");
            }
            __syncthreads();
            uint32_t bsb = smaddr(&Bs2[(kt&1)*(T2_*TW_LDS1)]);
            #pragma unroll
            for (int kk=0; kk<2; kk++){
                uint32_t af[2][4];
                #pragma unroll
                for (int mt=0; mt<2; mt++)
                    ldsm_x4(af[mt], t1b + (uint32_t)(((a_row + mt*16)*TW_T1_LDS) + kt*32 + kk*16 + a_ko)*2u);
                #pragma unroll
                for (int ntp=0; ntp<2; ntp++){
                    uint32_t bf[4];
                    ldsm_x4(bf, bsb + (uint32_t)(((b2_row + ntp*16)*TW_LDS1) + kk*16 + b_ko)*2u);
                    #pragma unroll
                    for (int mt=0; mt<2; mt++){
                        mma16816(acc2[mt][2*ntp],   af[mt], bf);
                        mma16816(acc2[mt][2*ntp+1], af[mt], bf+2);
                    }
                }
            }
            __syncthreads();
        }
    }

    // logit + sigmoid + scatter
    #pragma unroll
    for (int mt=0; mt<2; mt++){
        float s0 = 0.f, s1 = 0.f;
        #pragma unroll
        for (int nt=0; nt<4; nt++){
            int c = wn*32 + nt*8 + tg*2;
            float b0 = tb2[c], b1 = tb2[c+1];
            float w0 = wo[c],  w1 = wo[c+1];
            s0 += fmaxf(acc2[mt][nt][0] + b0, 0.f)*w0 + fmaxf(acc2[mt][nt][1] + b1, 0.f)*w1;
            s1 += fmaxf(acc2[mt][nt][2] + b0, 0.f)*w0 + fmaxf(acc2[mt][nt][3] + b1, 0.f)*w1;
        }
        s0 += __shfl_xor_sync(0xffffffffu, s0, 1);
        s0 += __shfl_xor_sync(0xffffffffu, s0, 2);
        s1 += __shfl_xor_sync(0xffffffffu, s1, 1);
        s1 += __shfl_xor_sync(0xffffffffu, s1, 2);
        if (tg == 0){
            int r = wm*32 + mt*16 + g;
            atomicAdd(&srow[r],     s0);
            atomicAdd(&srow[r + 8], s1);
        }
    }
    __syncthreads();

    if (tid < limit){
        float logit = srow[tid] + Tbo[d];
        out[permd[m0 + tid]] = 1.f / (1.f + expf(-logit));
    }
}

// ---------------- launch ----------------------------------------------------
extern "C" void kernel_launch(void* const* d_in, const int* in_sizes, int n_in,
                              void* d_out, int out_size)
{
    const float* x    = (const float*)d_in[0];
    const int*   dom  = (const int*)  d_in[1];
    const float* W1   = (const float*)d_in[2];
    const float* b1   = (const float*)d_in[3];
    const float* W2   = (const float*)d_in[4];
    const float* b2   = (const float*)d_in[5];
    const float* TW1  = (const float*)d_in[6];
    const float* Tb1  = (const float*)d_in[7];
    const float* TW2  = (const float*)d_in[8];
    const float* Tb2  = (const float*)d_in[9];
    const float* TWo  = (const float*)d_in[10];
    const float* Tbo  = (const float*)d_in[11];
    float* out = (float*)d_out;

    void *p;
    cudaGetSymbolAddress(&p, g_xb);   bf16* xb   = (bf16*)p;
    cudaGetSymbolAddress(&p, g_w1t);  bf16* w1t  = (bf16*)p;
    cudaGetSymbolAddress(&p, g_w2t);  bf16* w2t  = (bf16*)p;
    cudaGetSymbolAddress(&p, g_h1);   bf16* h1   = (bf16*)p;
    cudaGetSymbolAddress(&p, g_h2);   bf16* h2   = (bf16*)p;

    const int GEMM_SMEM = (2*128*72 + 2*128*72) * (int)sizeof(bf16);  // 73728
    cudaFuncSetAttribute(gemm_bf16_kernel<true>,  cudaFuncAttributeMaxDynamicSharedMemorySize, GEMM_SMEM);
    cudaFuncSetAttribute(gemm_bf16_kernel<false>, cudaFuncAttributeMaxDynamicSharedMemorySize, GEMM_SMEM);
    cudaFuncSetAttribute(tower_kernel, cudaFuncAttributeMaxDynamicSharedMemorySize, TW_SMEM);

    // 1) mega prep: scatter (fixed-stride buckets) + x convert + transposes
    prep_kernel<<<PREP_BLOCKS, 256>>>(dom, (const float4*)x, W1, W2, TW1, TW2);

    // 2) bottom MLP (GEMM1 carries the cursor->counts fixup)
    gemm_bf16_kernel<true><<<dim3(B_/128, H1_/128), 256, GEMM_SMEM>>>(
        xb, w1t, b1, h1, B_, H1_, FIN_);
    gemm_bf16_kernel<false><<<dim3(B_/128, H2_/128), 256, GEMM_SMEM>>>(
        h1, w2t, b2, h2, B_, H2_, H1_);

    // 3) fused towers: L1+L2+L3 + sigmoid + scatter
    tower_kernel<<<dim3(B_/TW_BM, D_), 256, TW_SMEM>>>(Tb1, Tb2, TWo, Tbo, out);
}

// round 12
// speedup vs baseline: 1.0651x; 1.0308x over previous
#include <cuda_runtime.h>
#include <cuda_bf16.h>
#include <math.h>
#include <stdint.h>

typedef __nv_bfloat16 bf16;

#define B_    16384
#define FIN_  640
#define H1_   1024
#define H2_   512
#define T1_   256
#define T2_   128
#define D_    8

#define DEVFN static __device__ __forceinline__

// ---------------- scratch (static device globals; no allocs allowed) -------
__device__ bf16 g_xb  [B_*FIN_];
__device__ bf16 g_w1t [H1_*FIN_];
__device__ bf16 g_w2t [H2_*H1_];
__device__ bf16 g_tw1t[D_*T1_*H2_];
__device__ bf16 g_tw2t[D_*T2_*T1_];
__device__ bf16 g_h1  [B_*H1_];
__device__ bf16 g_h2  [B_*H2_];
__device__ int  g_perm[D_*B_];      // fixed-stride buckets: domain d at d*B_
__device__ int  g_counts[D_];
__device__ int  g_cursor[D_];       // zeroed by GEMM1 fixup each call

// ---------------- helpers ---------------------------------------------------
DEVFN uint32_t smaddr(const void* p){ return (uint32_t)__cvta_generic_to_shared(p); }

DEVFN void cp16(uint32_t s, const void* g){
    asm volatile("cp.async.cg.shared.global [%0], [%1], 16;" :: "r"(s), "l"(g));
}
DEVFN void cp_commit(){ asm volatile("cp.async.commit_group;"); }

DEVFN void ldsm_x4(uint32_t* r, uint32_t addr){
    asm volatile("ldmatrix.sync.aligned.m8n8.x4.shared.b16 {%0,%1,%2,%3}, [%4];"
        : "=r"(r[0]), "=r"(r[1]), "=r"(r[2]), "=r"(r[3]) : "r"(addr));
}

DEVFN void mma16816(float* d, const uint32_t* a, const uint32_t* b){
    asm volatile(
        "mma.sync.aligned.m16n8k16.row.col.f32.bf16.bf16.f32 "
        "{%0,%1,%2,%3}, {%4,%5,%6,%7}, {%8,%9}, {%0,%1,%2,%3};\n"
        : "+f"(d[0]), "+f"(d[1]), "+f"(d[2]), "+f"(d[3])
        : "r"(a[0]), "r"(a[1]), "r"(a[2]), "r"(a[3]), "r"(b[0]), "r"(b[1]));
}

// ---------------- mega prep: scatter + x convert + weight transposes --------
#define PREP_SCATTER  64
#define PREP_CONVX    2560
#define PREP_TILES    2432
#define PREP_BLOCKS   (PREP_SCATTER + PREP_CONVX + PREP_TILES)

DEVFN void trans_tile(const float* __restrict__ src, bf16* __restrict__ dst,
                      int K, int N, int ky, int nx, int tx, int ty,
                      float (*tile)[33]){
    int k0 = ky*32, n0 = nx*32;
    #pragma unroll
    for (int i=0;i<32;i+=8)
        tile[ty+i][tx] = src[(size_t)(k0+ty+i)*N + n0 + tx];
    __syncthreads();
    #pragma unroll
    for (int i=0;i<32;i+=8)
        dst[(size_t)(n0+ty+i)*K + k0 + tx] = __float2bfloat16(tile[tx][ty+i]);
}

__global__ __launch_bounds__(256,1) void prep_kernel(
    const int* __restrict__ dom,
    const float4* __restrict__ x4,
    const float* __restrict__ W1, const float* __restrict__ W2,
    const float* __restrict__ TW1, const float* __restrict__ TW2)
{
    __shared__ float tile[32][33];
    __shared__ int sh[D_], sbase[D_], scur[D_];
    int bid = blockIdx.x, tid = threadIdx.x;

    if (bid < PREP_SCATTER){
        if (tid < D_){ sh[tid]=0; scur[tid]=0; }
        __syncthreads();
        int i = bid*256 + tid;
        int d = dom[i];
        atomicAdd(&sh[d], 1);
        __syncthreads();
        if (tid < D_ && sh[tid] > 0)
            sbase[tid] = atomicAdd(&g_cursor[tid], sh[tid]);
        __syncthreads();
        int p = atomicAdd(&scur[d], 1);
        g_perm[d*B_ + sbase[d] + p] = i;
        return;
    }
    if (bid < PREP_SCATTER + PREP_CONVX){
        int i0 = (bid - PREP_SCATTER)*1024 + tid;
        #pragma unroll
        for (int k=0;k<4;k++){
            int i = i0 + k*256;
            float4 v = x4[i];
            __nv_bfloat162* o = (__nv_bfloat162*)g_xb + (size_t)i*2;
            o[0] = __floats2bfloat162_rn(v.x, v.y);
            o[1] = __floats2bfloat162_rn(v.z, v.w);
        }
        return;
    }
    int t = bid - (PREP_SCATTER + PREP_CONVX);
    int tx = tid & 31, ty = tid >> 5;
    if (t < 640){
        trans_tile(W1, g_w1t, FIN_, H1_, t/32, t%32, tx, ty, tile);
    } else if (t < 1152){
        int t2 = t - 640;
        trans_tile(W2, g_w2t, H1_, H2_, t2/16, t2%16, tx, ty, tile);
    } else if (t < 2176){
        int t3 = t - 1152;
        int z = t3 >> 7, r = t3 & 127;
        trans_tile(TW1 + (size_t)z*H2_*T1_, g_tw1t + (size_t)z*T1_*H2_,
                   H2_, T1_, r/8, r%8, tx, ty, tile);
    } else {
        int t4 = t - 2176;
        int z = t4 >> 5, r = t4 & 31;
        trans_tile(TW2 + (size_t)z*T1_*T2_, g_tw2t + (size_t)z*T2_*T1_,
                   T1_, T2_, r/4, r%4, tx, ty, tile);
    }
}

// ---------------- HMMA GEMM (proven config, FROZEN): 128x128, 2 CTAs/SM ----
template<bool FIXUP>
__global__ __launch_bounds__(256,2) void gemm_bf16_kernel(
    const bf16* __restrict__ A,
    const bf16* __restrict__ Bt,
    const float* __restrict__ bias,
    bf16* __restrict__ Cout,
    int M, int N, int K)
{
    constexpr int BM=128, BN=128, BK=64, LDS=BK+8;
    constexpr int STG = BM*LDS;
    extern __shared__ bf16 sm[];
    bf16* As = sm;
    bf16* Bs = sm + 2*STG;

    int tid = threadIdx.x;
    if (FIXUP && blockIdx.x==0 && blockIdx.y==0 && tid==0){
        #pragma unroll
        for (int d=0; d<D_; d++){
            g_counts[d] = g_cursor[d];
            g_cursor[d] = 0;
        }
    }

    int m0 = blockIdx.x*BM;
    int n0 = blockIdx.y*BN;

    auto load_tile = [&](int st, int kt){
        int k0 = kt*BK;
        #pragma unroll
        for (int i=0;i<4;i++){
            int v = tid + 256*i;
            int r = v>>3, c = v&7;
            cp16(smaddr(&As[st*STG + r*LDS + c*8]), A + (size_t)(m0 + r)*K + k0 + c*8);
        }
        #pragma unroll
        for (int i=0;i<4;i++){
            int v = tid + 256*i;
            int r = v>>3, c = v&7;
            cp16(smaddr(&Bs[st*STG + r*LDS + c*8]), Bt + (size_t)(n0 + r)*K + k0 + c*8);
        }
    };

    int warp = tid>>5, lane = tid&31;
    int wm = warp & 3, wn = warp >> 2;     // 4 x 2
    int g  = lane>>2,  tg = lane&3;

    int a_row = wm*32 + (lane&7) + ((lane&8)?8:0);
    int a_ko  = (lane&16)?8:0;
    int b_row = wn*64 + (lane&7) + ((lane&16)?8:0);
    int b_ko  = (lane&8)?8:0;

    float acc[2][8][4];
    #pragma unroll
    for (int a=0;a<2;a++)
        #pragma unroll
        for (int b=0;b<8;b++)
            #pragma unroll
            for (int c=0;c<4;c++) acc[a][b][c]=0.f;

    const int KT = K/BK;
    load_tile(0, 0); cp_commit();
    for (int kt=0; kt<KT; kt++){
        if (kt+1 < KT){
            load_tile((kt+1)&1, kt+1); cp_commit();
            asm volatile("cp.async.wait_group 1;");
        } else {
            asm volatile("cp.async.wait_group 0;");
        }
        __syncthreads();
        uint32_t asb = smaddr(&As[(kt&1)*STG]);
        uint32_t bsb = smaddr(&Bs[(kt&1)*STG]);
        #pragma unroll
        for (int kk=0; kk<4; kk++){
            uint32_t af[2][4];
            #pragma unroll
            for (int mt=0; mt<2; mt++)
                ldsm_x4(af[mt], asb + (uint32_t)(((a_row + mt*16)*LDS) + kk*16 + a_ko)*2u);
            #pragma unroll
            for (int ntp=0; ntp<4; ntp++){
                uint32_t bf[4];
                ldsm_x4(bf, bsb + (uint32_t)(((b_row + ntp*16)*LDS) + kk*16 + b_ko)*2u);
                #pragma unroll
                for (int mt=0; mt<2; mt++){
                    mma16816(acc[mt][2*ntp],   af[mt], bf);
                    mma16816(acc[mt][2*ntp+1], af[mt], bf+2);
                }
            }
        }
        __syncthreads();
    }

    #pragma unroll
    for (int nt=0; nt<8; nt++){
        int c = n0 + wn*64 + nt*8 + tg*2;
        float bv0 = bias[c], bv1 = bias[c+1];
        #pragma unroll
        for (int mt=0; mt<2; mt++){
            int rl0 = wm*32 + mt*16 + g;
            int rl1 = rl0 + 8;
            float v00 = fmaxf(acc[mt][nt][0] + bv0, 0.f);
            float v01 = fmaxf(acc[mt][nt][1] + bv1, 0.f);
            float v10 = fmaxf(acc[mt][nt][2] + bv0, 0.f);
            float v11 = fmaxf(acc[mt][nt][3] + bv1, 0.f);
            *(__nv_bfloat162*)&Cout[(size_t)(m0+rl0)*N + c] = __floats2bfloat162_rn(v00, v01);
            *(__nv_bfloat162*)&Cout[(size_t)(m0+rl1)*N + c] = __floats2bfloat162_rn(v10, v11);
        }
    }
}

// ---------------- FUSED tower v3: compact grid + single-sync pipeline ------
#define TW_BM      64
#define TW_LDS1    40
#define TW_PIPE_H  (2*(TW_BM + T1_)*TW_LDS1)
#define TW_T1_LDS  264
#define TW_SMEM    ((TW_PIPE_H + TW_BM*TW_T1_LDS) * 2)
#define TW_GRID    (B_/TW_BM + D_)     /* 264: enough for any count split */

__global__ __launch_bounds__(256,2) void tower_kernel(
    const float* __restrict__ Tb1,
    const float* __restrict__ Tb2,
    const float* __restrict__ TWo,
    const float* __restrict__ Tbo,
    float* __restrict__ out)
{
    constexpr int BK=32;
    constexpr int ASTG = TW_BM*TW_LDS1;
    constexpr int BSTG = T1_*TW_LDS1;
    extern __shared__ bf16 sm[];
    bf16* As  = sm;
    bf16* Bs  = sm + 2*ASTG;
    bf16* Bs2 = sm;
    bf16* t1s = sm + TW_PIPE_H;
    __shared__ int s_rows[TW_BM];
    __shared__ float srow[TW_BM];

    int tid = threadIdx.x;

    // compact block -> (domain, m-block) mapping from g_counts (uniform scan)
    int b = blockIdx.x;
    int d = 0, mblk = -1;
    {
        int base = 0;
        #pragma unroll
        for (int dd=0; dd<D_; dd++){
            int nb = (g_counts[dd] + TW_BM - 1) / TW_BM;
            if (mblk < 0 && b < base + nb){ d = dd; mblk = b - base; }
            base += nb;
        }
        if (mblk < 0) return;
    }
    int cnt = g_counts[d];
    int m0 = mblk*TW_BM;
    const int* permd = g_perm + d*B_;
    int limit = min(TW_BM, cnt - m0);
    if (tid < TW_BM){
        s_rows[tid] = (tid < limit) ? permd[m0 + tid] : permd[m0];
        srow[tid] = 0.f;
    }
    __syncthreads();

    const bf16* Bt1 = g_tw1t + (size_t)d*T1_*H2_;
    const bf16* Bt2 = g_tw2t + (size_t)d*T2_*T1_;
    const float* tb1 = Tb1 + d*T1_;
    const float* tb2 = Tb2 + d*T2_;
    const float* wo  = TWo + d*T2_;

    int warp = tid>>5, lane = tid&31;
    int wm = warp & 1, wn = warp >> 1;     // 2 x 4
    int g  = lane>>2,  tg = lane&3;

    int a_row = wm*32 + (lane&7) + ((lane&8)?8:0);
    int a_ko  = (lane&16)?8:0;
    int b_row = wn*64 + (lane&7) + ((lane&16)?8:0);
    int b_ko  = (lane&8)?8:0;

    float acc[2][8][4];
    #pragma unroll
    for (int a=0;a<2;a++)
        #pragma unroll
        for (int b2=0;b2<8;b2++)
            #pragma unroll
            for (int c=0;c<4;c++) acc[a][b2][c]=0.f;

    // phase 1: t1 = relu(h2 @ TW1^T + Tb1), single-sync pipeline
    auto load1 = [&](int st, int kt){
        int k0 = kt*BK;
        {
            int r = tid>>2, c = tid&3;
            cp16(smaddr(&As[st*ASTG + r*TW_LDS1 + c*8]), g_h2 + (size_t)s_rows[r]*H2_ + k0 + c*8);
        }
        #pragma unroll
        for (int i=0;i<4;i++){
            int v = tid + 256*i;
            int r = v>>2, c = v&3;
            cp16(smaddr(&Bs[st*BSTG + r*TW_LDS1 + c*8]), Bt1 + (size_t)r*H2_ + k0 + c*8);
        }
    };

    {
        constexpr int KT = H2_/BK;   // 16
        load1(0, 0); cp_commit();
        for (int kt=0; kt<KT; kt++){
            asm volatile("cp.async.wait_group 0;");   // only load(kt) pending
            __syncthreads();                          // all warps done compute(kt-1); data visible
            if (kt+1 < KT){ load1((kt+1)&1, kt+1); cp_commit(); }   // overlaps compute(kt)
            uint32_t asb = smaddr(&As[(kt&1)*ASTG]);
            uint32_t bsb = smaddr(&Bs[(kt&1)*BSTG]);
            #pragma unroll
            for (int kk=0; kk<2; kk++){
                uint32_t af[2][4];
                #pragma unroll
                for (int mt=0; mt<2; mt++)
                    ldsm_x4(af[mt], asb + (uint32_t)(((a_row + mt*16)*TW_LDS1) + kk*16 + a_ko)*2u);
                #pragma unroll
                for (int ntp=0; ntp<4; ntp++){
                    uint32_t bf[4];
                    ldsm_x4(bf, bsb + (uint32_t)(((b_row + ntp*16)*TW_LDS1) + kk*16 + b_ko)*2u);
                    #pragma unroll
                    for (int mt=0; mt<2; mt++){
                        mma16816(acc[mt][2*ntp],   af[mt], bf);
                        mma16816(acc[mt][2*ntp+1], af[mt], bf+2);
                    }
                }
            }
        }
    }
    __syncthreads();   // all compute(KT-1) done before t1 writes overwrite nothing (t1s separate) — orders t1s stores below vs phase2 reads

    #pragma unroll
    for (int nt=0; nt<8; nt++){
        int c = wn*64 + nt*8 + tg*2;
        float bv0 = tb1[c], bv1 = tb1[c+1];
        #pragma unroll
        for (int mt=0; mt<2; mt++){
            int rl0 = wm*32 + mt*16 + g;
            int rl1 = rl0 + 8;
            float v00 = fmaxf(acc[mt][nt][0] + bv0, 0.f);
            float v01 = fmaxf(acc[mt][nt][1] + bv1, 0.f);
            float v10 = fmaxf(acc[mt][nt][2] + bv0, 0.f);
            float v11 = fmaxf(acc[mt][nt][3] + bv1, 0.f);
            *(__nv_bfloat162*)&t1s[rl0*TW_T1_LDS + c] = __floats2bfloat162_rn(v00, v01);
            *(__nv_bfloat162*)&t1s[rl1*TW_T1_LDS + c] = __floats2bfloat162_rn(v10, v11);
        }
    }
    __syncthreads();   // t1 complete; pipeline region free for phase2 B

    // phase 2: t2 = relu(t1 @ TW2^T + Tb2), single-sync pipeline
    int b2_row = wn*32 + (lane&7) + ((lane&16)?8:0);
    float acc2[2][4][4];
    #pragma unroll
    for (int a=0;a<2;a++)
        #pragma unroll
        for (int b2=0;b2<4;b2++)
            #pragma unroll
            for (int c=0;c<4;c++) acc2[a][b2][c]=0.f;

    auto load2 = [&](int st, int kt){
        int k0 = kt*BK;
        #pragma unroll
        for (int i=0;i<2;i++){
            int v = tid + 256*i;
            int r = v>>2, c = v&3;
            cp16(smaddr(&Bs2[st*(T2_*TW_LDS1) + r*TW_LDS1 + c*8]), Bt2 + (size_t)r*T1_ + k0 + c*8);
        }
    };

    {
        constexpr int KT2 = T1_/BK;   // 8
        uint32_t t1b = smaddr(t1s);
        load2(0, 0); cp_commit();
        for (int kt=0; kt<KT2; kt++){
            asm volatile("cp.async.wait_group 0;");
            __syncthreads();
            if (kt+1 < KT2){ load2((kt+1)&1, kt+1); cp_commit(); }
            uint32_t bsb = smaddr(&Bs2[(kt&1)*(T2_*TW_LDS1)]);
            #pragma unroll
            for (int kk=0; kk<2; kk++){
                uint32_t af[2][4];
                #pragma unroll
                for (int mt=0; mt<2; mt++)
                    ldsm_x4(af[mt], t1b + (uint32_t)(((a_row + mt*16)*TW_T1_LDS) + kt*32 + kk*16 + a_ko)*2u);
                #pragma unroll
                for (int ntp=0; ntp<2; ntp++){
                    uint32_t bf[4];
                    ldsm_x4(bf, bsb + (uint32_t)(((b2_row + ntp*16)*TW_LDS1) + kk*16 + b_ko)*2u);
                    #pragma unroll
                    for (int mt=0; mt<2; mt++){
                        mma16816(acc2[mt][2*ntp],   af[mt], bf);
                        mma16816(acc2[mt][2*ntp+1], af[mt], bf+2);
                    }
                }
            }
        }
    }

    // logit + sigmoid + scatter
    #pragma unroll
    for (int mt=0; mt<2; mt++){
        float s0 = 0.f, s1 = 0.f;
        #pragma unroll
        for (int nt=0; nt<4; nt++){
            int c = wn*32 + nt*8 + tg*2;
            float b0 = tb2[c], b1 = tb2[c+1];
            float w0 = wo[c],  w1 = wo[c+1];
            s0 += fmaxf(acc2[mt][nt][0] + b0, 0.f)*w0 + fmaxf(acc2[mt][nt][1] + b1, 0.f)*w1;
            s1 += fmaxf(acc2[mt][nt][2] + b0, 0.f)*w0 + fmaxf(acc2[mt][nt][3] + b1, 0.f)*w1;
        }
        s0 += __shfl_xor_sync(0xffffffffu, s0, 1);
        s0 += __shfl_xor_sync(0xffffffffu, s0, 2);
        s1 += __shfl_xor_sync(0xffffffffu, s1, 1);
        s1 += __shfl_xor_sync(0xffffffffu, s1, 2);
        if (tg == 0){
            int r = wm*32 + mt*16 + g;
            atomicAdd(&srow[r],     s0);
            atomicAdd(&srow[r + 8], s1);
        }
    }
    __syncthreads();

    if (tid < limit){
        float logit = srow[tid] + Tbo[d];
        out[permd[m0 + tid]] = 1.f / (1.f + expf(-logit));
    }
}

// ---------------- launch ----------------------------------------------------
extern "C" void kernel_launch(void* const* d_in, const int* in_sizes, int n_in,
                              void* d_out, int out_size)
{
    const float* x    = (const float*)d_in[0];
    const int*   dom  = (const int*)  d_in[1];
    const float* W1   = (const float*)d_in[2];
    const float* b1   = (const float*)d_in[3];
    const float* W2   = (const float*)d_in[4];
    const float* b2   = (const float*)d_in[5];
    const float* TW1  = (const float*)d_in[6];
    const float* Tb1  = (const float*)d_in[7];
    const float* TW2  = (const float*)d_in[8];
    const float* Tb2  = (const float*)d_in[9];
    const float* TWo  = (const float*)d_in[10];
    const float* Tbo  = (const float*)d_in[11];
    float* out = (float*)d_out;

    void *p;
    cudaGetSymbolAddress(&p, g_xb);   bf16* xb   = (bf16*)p;
    cudaGetSymbolAddress(&p, g_w1t);  bf16* w1t  = (bf16*)p;
    cudaGetSymbolAddress(&p, g_w2t);  bf16* w2t  = (bf16*)p;
    cudaGetSymbolAddress(&p, g_h1);   bf16* h1   = (bf16*)p;
    cudaGetSymbolAddress(&p, g_h2);   bf16* h2   = (bf16*)p;

    const int GEMM_SMEM = (2*128*72 + 2*128*72) * (int)sizeof(bf16);  // 73728
    cudaFuncSetAttribute(gemm_bf16_kernel<true>,  cudaFuncAttributeMaxDynamicSharedMemorySize, GEMM_SMEM);
    cudaFuncSetAttribute(gemm_bf16_kernel<false>, cudaFuncAttributeMaxDynamicSharedMemorySize, GEMM_SMEM);
    cudaFuncSetAttribute(tower_kernel, cudaFuncAttributeMaxDynamicSharedMemorySize, TW_SMEM);

    // 1) mega prep: scatter (fixed-stride buckets) + x convert + transposes
    prep_kernel<<<PREP_BLOCKS, 256>>>(dom, (const float4*)x, W1, W2, TW1, TW2);

    // 2) bottom MLP (GEMM1 carries the cursor->counts fixup)
    gemm_bf16_kernel<true><<<dim3(B_/128, H1_/128), 256, GEMM_SMEM>>>(
        xb, w1t, b1, h1, B_, H1_, FIN_);
    gemm_bf16_kernel<false><<<dim3(B_/128, H2_/128), 256, GEMM_SMEM>>>(
        h1, w2t, b2, h2, B_, H2_, H1_);

    // 3) fused towers: compact grid, single-sync pipelines
    tower_kernel<<<TW_GRID, 256, TW_SMEM>>>(Tb1, Tb2, TWo, Tbo, out);
}

// round 14
// speedup vs baseline: 1.0691x; 1.0038x over previous
#include <cuda_runtime.h>
#include <cuda_bf16.h>
#include <math.h>
#include <stdint.h>

typedef __nv_bfloat16 bf16;

#define B_    16384
#define FIN_  640
#define H1_   1024
#define H2_   512
#define T1_   256
#define T2_   128
#define D_    8

#define DEVFN static __device__ __forceinline__

// ---------------- scratch (static device globals; no allocs allowed) -------
__device__ bf16 g_xb  [B_*FIN_];
__device__ bf16 g_w1t [H1_*FIN_];
__device__ bf16 g_w2t [H2_*H1_];
__device__ bf16 g_tw1t[D_*T1_*H2_];
__device__ bf16 g_tw2t[D_*T2_*T1_];
__device__ bf16 g_h1  [B_*H1_];
__device__ bf16 g_h2  [B_*H2_];
__device__ int  g_perm[D_*B_];      // fixed-stride buckets: domain d at d*B_
__device__ int  g_counts[D_];
__device__ int  g_cursor[D_];       // zeroed by GEMM1 fixup each call

// ---------------- helpers ---------------------------------------------------
DEVFN uint32_t smaddr(const void* p){ return (uint32_t)__cvta_generic_to_shared(p); }

DEVFN void cp16(uint32_t s, const void* g){
    asm volatile("cp.async.cg.shared.global [%0], [%1], 16;" :: "r"(s), "l"(g));
}
DEVFN void cp_commit(){ asm volatile("cp.async.commit_group;"); }

DEVFN void ldsm_x4(uint32_t* r, uint32_t addr){
    asm volatile("ldmatrix.sync.aligned.m8n8.x4.shared.b16 {%0,%1,%2,%3}, [%4];"
        : "=r"(r[0]), "=r"(r[1]), "=r"(r[2]), "=r"(r[3]) : "r"(addr));
}

DEVFN void mma16816(float* d, const uint32_t* a, const uint32_t* b){
    asm volatile(
        "mma.sync.aligned.m16n8k16.row.col.f32.bf16.bf16.f32 "
        "{%0,%1,%2,%3}, {%4,%5,%6,%7}, {%8,%9}, {%0,%1,%2,%3};\n"
        : "+f"(d[0]), "+f"(d[1]), "+f"(d[2]), "+f"(d[3])
        : "r"(a[0]), "r"(a[1]), "r"(a[2]), "r"(a[3]), "r"(b[0]), "r"(b[1]));
}

// ---------------- mega prep: scatter + x convert + weight transposes --------
#define PREP_SCATTER  64
#define PREP_CONVX    2560
#define PREP_TILES    2432
#define PREP_BLOCKS   (PREP_SCATTER + PREP_CONVX + PREP_TILES)

DEVFN void trans_tile(const float* __restrict__ src, bf16* __restrict__ dst,
                      int K, int N, int ky, int nx, int tx, int ty,
                      float (*tile)[33]){
    int k0 = ky*32, n0 = nx*32;
    #pragma unroll
    for (int i=0;i<32;i+=8)
        tile[ty+i][tx] = src[(size_t)(k0+ty+i)*N + n0 + tx];
    __syncthreads();
    #pragma unroll
    for (int i=0;i<32;i+=8)
        dst[(size_t)(n0+ty+i)*K + k0 + tx] = __float2bfloat16(tile[tx][ty+i]);
}

__global__ __launch_bounds__(256,1) void prep_kernel(
    const int* __restrict__ dom,
    const float4* __restrict__ x4,
    const float* __restrict__ W1, const float* __restrict__ W2,
    const float* __restrict__ TW1, const float* __restrict__ TW2)
{
    __shared__ float tile[32][33];
    __shared__ int sh[D_], sbase[D_], scur[D_];
    int bid = blockIdx.x, tid = threadIdx.x;

    if (bid < PREP_SCATTER){
        if (tid < D_){ sh[tid]=0; scur[tid]=0; }
        __syncthreads();
        int i = bid*256 + tid;
        int d = dom[i];
        atomicAdd(&sh[d], 1);
        __syncthreads();
        if (tid < D_ && sh[tid] > 0)
            sbase[tid] = atomicAdd(&g_cursor[tid], sh[tid]);
        __syncthreads();
        int p = atomicAdd(&scur[d], 1);
        g_perm[d*B_ + sbase[d] + p] = i;
        return;
    }
    if (bid < PREP_SCATTER + PREP_CONVX){
        int i0 = (bid - PREP_SCATTER)*1024 + tid;
        #pragma unroll
        for (int k=0;k<4;k++){
            int i = i0 + k*256;
            float4 v = x4[i];
            __nv_bfloat162* o = (__nv_bfloat162*)g_xb + (size_t)i*2;
            o[0] = __floats2bfloat162_rn(v.x, v.y);
            o[1] = __floats2bfloat162_rn(v.z, v.w);
        }
        return;
    }
    int t = bid - (PREP_SCATTER + PREP_CONVX);
    int tx = tid & 31, ty = tid >> 5;
    if (t < 640){
        trans_tile(W1, g_w1t, FIN_, H1_, t/32, t%32, tx, ty, tile);
    } else if (t < 1152){
        int t2 = t - 640;
        trans_tile(W2, g_w2t, H1_, H2_, t2/16, t2%16, tx, ty, tile);
    } else if (t < 2176){
        int t3 = t - 1152;
        int z = t3 >> 7, r = t3 & 127;
        trans_tile(TW1 + (size_t)z*H2_*T1_, g_tw1t + (size_t)z*T1_*H2_,
                   H2_, T1_, r/8, r%8, tx, ty, tile);
    } else {
        int t4 = t - 2176;
        int z = t4 >> 5, r = t4 & 31;
        trans_tile(TW2 + (size_t)z*T1_*T2_, g_tw2t + (size_t)z*T2_*T1_,
                   T1_, T2_, r/4, r%4, tx, ty, tile);
    }
}

// ---------------- HMMA GEMM (proven config, FROZEN): 128x128, 2 CTAs/SM ----
template<bool FIXUP>
__global__ __launch_bounds__(256,2) void gemm_bf16_kernel(
    const bf16* __restrict__ A,
    const bf16* __restrict__ Bt,
    const float* __restrict__ bias,
    bf16* __restrict__ Cout,
    int M, int N, int K)
{
    constexpr int BM=128, BN=128, BK=64, LDS=BK+8;
    constexpr int STG = BM*LDS;
    extern __shared__ bf16 sm[];
    bf16* As = sm;
    bf16* Bs = sm + 2*STG;

    int tid = threadIdx.x;
    if (FIXUP && blockIdx.x==0 && blockIdx.y==0 && tid==0){
        #pragma unroll
        for (int d=0; d<D_; d++){
            g_counts[d] = g_cursor[d];
            g_cursor[d] = 0;
        }
    }

    int m0 = blockIdx.x*BM;
    int n0 = blockIdx.y*BN;

    auto load_tile = [&](int st, int kt){
        int k0 = kt*BK;
        #pragma unroll
        for (int i=0;i<4;i++){
            int v = tid + 256*i;
            int r = v>>3, c = v&7;
            cp16(smaddr(&As[st*STG + r*LDS + c*8]), A + (size_t)(m0 + r)*K + k0 + c*8);
        }
        #pragma unroll
        for (int i=0;i<4;i++){
            int v = tid + 256*i;
            int r = v>>3, c = v&7;
            cp16(smaddr(&Bs[st*STG + r*LDS + c*8]), Bt + (size_t)(n0 + r)*K + k0 + c*8);
        }
    };

    int warp = tid>>5, lane = tid&31;
    int wm = warp & 3, wn = warp >> 2;     // 4 x 2
    int g  = lane>>2,  tg = lane&3;

    int a_row = wm*32 + (lane&7) + ((lane&8)?8:0);
    int a_ko  = (lane&16)?8:0;
    int b_row = wn*64 + (lane&7) + ((lane&16)?8:0);
    int b_ko  = (lane&8)?8:0;

    float acc[2][8][4];
    #pragma unroll
    for (int a=0;a<2;a++)
        #pragma unroll
        for (int b=0;b<8;b++)
            #pragma unroll
            for (int c=0;c<4;c++) acc[a][b][c]=0.f;

    const int KT = K/BK;
    load_tile(0, 0); cp_commit();
    for (int kt=0; kt<KT; kt++){
        if (kt+1 < KT){
            load_tile((kt+1)&1, kt+1); cp_commit();
            asm volatile("cp.async.wait_group 1;");
        } else {
            asm volatile("cp.async.wait_group 0;");
        }
        __syncthreads();
        uint32_t asb = smaddr(&As[(kt&1)*STG]);
        uint32_t bsb = smaddr(&Bs[(kt&1)*STG]);
        #pragma unroll
        for (int kk=0; kk<4; kk++){
            uint32_t af[2][4];
            #pragma unroll
            for (int mt=0; mt<2; mt++)
                ldsm_x4(af[mt], asb + (uint32_t)(((a_row + mt*16)*LDS) + kk*16 + a_ko)*2u);
            #pragma unroll
            for (int ntp=0; ntp<4; ntp++){
                uint32_t bf[4];
                ldsm_x4(bf, bsb + (uint32_t)(((b_row + ntp*16)*LDS) + kk*16 + b_ko)*2u);
                #pragma unroll
                for (int mt=0; mt<2; mt++){
                    mma16816(acc[mt][2*ntp],   af[mt], bf);
                    mma16816(acc[mt][2*ntp+1], af[mt], bf+2);
                }
            }
        }
        __syncthreads();
    }

    #pragma unroll
    for (int nt=0; nt<8; nt++){
        int c = n0 + wn*64 + nt*8 + tg*2;
        float bv0 = bias[c], bv1 = bias[c+1];
        #pragma unroll
        for (int mt=0; mt<2; mt++){
            int rl0 = wm*32 + mt*16 + g;
            int rl1 = rl0 + 8;
            float v00 = fmaxf(acc[mt][nt][0] + bv0, 0.f);
            float v01 = fmaxf(acc[mt][nt][1] + bv1, 0.f);
            float v10 = fmaxf(acc[mt][nt][2] + bv0, 0.f);
            float v11 = fmaxf(acc[mt][nt][3] + bv1, 0.f);
            *(__nv_bfloat162*)&Cout[(size_t)(m0+rl0)*N + c] = __floats2bfloat162_rn(v00, v01);
            *(__nv_bfloat162*)&Cout[(size_t)(m0+rl1)*N + c] = __floats2bfloat162_rn(v10, v11);
        }
    }
}

// ---------------- FUSED tower v4: 3-stage single-sync pipelines ------------
#define TW_BM      64
#define TW_LDS1    40
#define TW_STAGES  3
#define TW_PIPE_H  (TW_STAGES*(TW_BM + T1_)*TW_LDS1)   /* 38400 halves */
#define TW_T1_LDS  264
#define TW_SMEM    ((TW_PIPE_H + TW_BM*TW_T1_LDS) * 2) /* 110592 B */
#define TW_GRID    (B_/TW_BM + D_)     /* 264 */

__global__ __launch_bounds__(256,2) void tower_kernel(
    const float* __restrict__ Tb1,
    const float* __restrict__ Tb2,
    const float* __restrict__ TWo,
    const float* __restrict__ Tbo,
    float* __restrict__ out)
{
    constexpr int BK=32;
    constexpr int ASTG = TW_BM*TW_LDS1;          // 2560
    constexpr int BSTG = T1_*TW_LDS1;            // 10240
    constexpr int STG1 = ASTG + BSTG;            // combined stage stride
    extern __shared__ bf16 sm[];
    bf16* P   = sm;                              // 3 combined stages [A|B]
    bf16* t1s = sm + TW_PIPE_H;
    __shared__ int s_rows[TW_BM];
    __shared__ float srow[TW_BM];

    int tid = threadIdx.x;

    // compact block -> (domain, m-block) from g_counts
    int b = blockIdx.x;
    int d = 0, mblk = -1;
    {
        int base = 0;
        #pragma unroll
        for (int dd=0; dd<D_; dd++){
            int nb = (g_counts[dd] + TW_BM - 1) / TW_BM;
            if (mblk < 0 && b < base + nb){ d = dd; mblk = b - base; }
            base += nb;
        }
        if (mblk < 0) return;
    }
    int cnt = g_counts[d];
    int m0 = mblk*TW_BM;
    const int* permd = g_perm + d*B_;
    int limit = min(TW_BM, cnt - m0);
    if (tid < TW_BM){
        s_rows[tid] = (tid < limit) ? permd[m0 + tid] : permd[m0];
        srow[tid] = 0.f;
    }
    __syncthreads();

    const bf16* Bt1 = g_tw1t + (size_t)d*T1_*H2_;
    const bf16* Bt2 = g_tw2t + (size_t)d*T2_*T1_;
    const float* tb1 = Tb1 + d*T1_;
    const float* tb2 = Tb2 + d*T2_;
    const float* wo  = TWo + d*T2_;

    int warp = tid>>5, lane = tid&31;
    int wm = warp & 1, wn = warp >> 1;     // 2 x 4
    int g  = lane>>2,  tg = lane&3;

    int a_row = wm*32 + (lane&7) + ((lane&8)?8:0);
    int a_ko  = (lane&16)?8:0;
    int b_row = wn*64 + (lane&7) + ((lane&16)?8:0);
    int b_ko  = (lane&8)?8:0;

    float acc[2][8][4];
    #pragma unroll
    for (int a=0;a<2;a++)
        #pragma unroll
        for (int b2=0;b2<8;b2++)
            #pragma unroll
            for (int c=0;c<4;c++) acc[a][b2][c]=0.f;

    // phase 1: t1 = relu(h2 @ TW1^T + Tb1); 3-stage, 1 sync/iter
    auto load1 = [&](int st, int kt){
        int k0 = kt*BK;
        bf16* As = P + st*STG1;
        bf16* Bs = As + ASTG;
        {
            int r = tid>>2, c = tid&3;
            cp16(smaddr(&As[r*TW_LDS1 + c*8]), g_h2 + (size_t)s_rows[r]*H2_ + k0 + c*8);
        }
        #pragma unroll
        for (int i=0;i<4;i++){
            int v = tid + 256*i;
            int r = v>>2, c = v&3;
            cp16(smaddr(&Bs[r*TW_LDS1 + c*8]), Bt1 + (size_t)r*H2_ + k0 + c*8);
        }
    };

    {
        constexpr int KT = H2_/BK;   // 16
        load1(0, 0); cp_commit();
        load1(1, 1); cp_commit();
        int cs = 0, ls = 2;
        for (int kt=0; kt<KT; kt++){
            if (kt+1 < KT) asm volatile("cp.async.wait_group 1;");
            else           asm volatile("cp.async.wait_group 0;");
            __syncthreads();                 // compute(kt-1) retired on all warps
            if (kt+2 < KT){ load1(ls, kt+2); cp_commit(); }  // stage ls last read at kt-1
            uint32_t asb = smaddr(P + cs*STG1);
            uint32_t bsb = asb + ASTG*2u;
            #pragma unroll
            for (int kk=0; kk<2; kk++){
                uint32_t af[2][4];
                #pragma unroll
                for (int mt=0; mt<2; mt++)
                    ldsm_x4(af[mt], asb + (uint32_t)(((a_row + mt*16)*TW_LDS1) + kk*16 + a_ko)*2u);
                #pragma unroll
                for (int ntp=0; ntp<4; ntp++){
                    uint32_t bf[4];
                    ldsm_x4(bf, bsb + (uint32_t)(((b_row + ntp*16)*TW_LDS1) + kk*16 + b_ko)*2u);
                    #pragma unroll
                    for (int mt=0; mt<2; mt++){
                        mma16816(acc[mt][2*ntp],   af[mt], bf);
                        mma16816(acc[mt][2*ntp+1], af[mt], bf+2);
                    }
                }
            }
            cs = (cs==2)?0:cs+1;
            ls = (ls==2)?0:ls+1;
        }
    }
    __syncthreads();

    #pragma unroll
    for (int nt=0; nt<8; nt++){
        int c = wn*64 + nt*8 + tg*2;
        float bv0 = tb1[c], bv1 = tb1[c+1];
        #pragma unroll
        for (int mt=0; mt<2; mt++){
            int rl0 = wm*32 + mt*16 + g;
            int rl1 = rl0 + 8;
            float v00 = fmaxf(acc[mt][nt][0] + bv0, 0.f);
            float v01 = fmaxf(acc[mt][nt][1] + bv1, 0.f);
            float v10 = fmaxf(acc[mt][nt][2] + bv0, 0.f);
            float v11 = fmaxf(acc[mt][nt][3] + bv1, 0.f);
            *(__nv_bfloat162*)&t1s[rl0*TW_T1_LDS + c] = __floats2bfloat162_rn(v00, v01);
            *(__nv_bfloat162*)&t1s[rl1*TW_T1_LDS + c] = __floats2bfloat162_rn(v10, v11);
        }
    }
    __syncthreads();   // t1 visible; pipeline region reusable

    // phase 2: t2 = relu(t1 @ TW2^T + Tb2); 3-stage, 1 sync/iter
    int b2_row = wn*32 + (lane&7) + ((lane&16)?8:0);
    float acc2[2][4][4];
    #pragma unroll
    for (int a=0;a<2;a++)
        #pragma unroll
        for (int b2=0;b2<4;b2++)
            #pragma unroll
            for (int c=0;c<4;c++) acc2[a][b2][c]=0.f;

    constexpr int B2STG = T2_*TW_LDS1;   // 5120
    auto load2 = [&](int st, int kt){
        int k0 = kt*BK;
        bf16* Bs2 = P + st*B2STG;
        #pragma unroll
        for (int i=0;i<2;i++){
            int v = tid + 256*i;
            int r = v>>2, c = v&3;
            cp16(smaddr(&Bs2[r*TW_LDS1 + c*8]), Bt2 + (size_t)r*T1_ + k0 + c*8);
        }
    };

    {
        constexpr int KT2 = T1_/BK;   // 8
        uint32_t t1b = smaddr(t1s);
        load2(0, 0); cp_commit();
        load2(1, 1); cp_commit();
        int cs = 0, ls = 2;
        for (int kt=0; kt<KT2; kt++){
            if (kt+1 < KT2) asm volatile("cp.async.wait_group 1;");
            else            asm volatile("cp.async.wait_group 0;");
            __syncthreads();
            if (kt+2 < KT2){ load2(ls, kt+2); cp_commit(); }
            uint32_t bsb = smaddr(P + cs*B2STG);
            #pragma unroll
            for (int kk=0; kk<2; kk++){
                uint32_t af[2][4];
                #pragma unroll
                for (int mt=0; mt<2; mt++)
                    ldsm_x4(af[mt], t1b + (uint32_t)(((a_row + mt*16)*TW_T1_LDS) + kt*32 + kk*16 + a_ko)*2u);
                #pragma unroll
                for (int ntp=0; ntp<2; ntp++){
                    uint32_t bf[4];
                    ldsm_x4(bf, bsb + (uint32_t)(((b2_row + ntp*16)*TW_LDS1) + kk*16 + b_ko)*2u);
                    #pragma unroll
                    for (int mt=0; mt<2; mt++){
                        mma16816(acc2[mt][2*ntp],   af[mt], bf);
                        mma16816(acc2[mt][2*ntp+1], af[mt], bf+2);
                    }
                }
            }
            cs = (cs==2)?0:cs+1;
            ls = (ls==2)?0:ls+1;
        }
    }

    // logit + sigmoid + scatter
    #pragma unroll
    for (int mt=0; mt<2; mt++){
        float s0 = 0.f, s1 = 0.f;
        #pragma unroll
        for (int nt=0; nt<4; nt++){
            int c = wn*32 + nt*8 + tg*2;
            float b0 = tb2[c], b1 = tb2[c+1];
            float w0 = wo[c],  w1 = wo[c+1];
            s0 += fmaxf(acc2[mt][nt][0] + b0, 0.f)*w0 + fmaxf(acc2[mt][nt][1] + b1, 0.f)*w1;
            s1 += fmaxf(acc2[mt][nt][2] + b0, 0.f)*w0 + fmaxf(acc2[mt][nt][3] + b1, 0.f)*w1;
        }
        s0 += __shfl_xor_sync(0xffffffffu, s0, 1);
        s0 += __shfl_xor_sync(0xffffffffu, s0, 2);
        s1 += __shfl_xor_sync(0xffffffffu, s1, 1);
        s1 += __shfl_xor_sync(0xffffffffu, s1, 2);
        if (tg == 0){
            int r = wm*32 + mt*16 + g;
            atomicAdd(&srow[r],     s0);
            atomicAdd(&srow[r + 8], s1);
        }
    }
    __syncthreads();

    if (tid < limit){
        float logit = srow[tid] + Tbo[d];
        out[permd[m0 + tid]] = 1.f / (1.f + expf(-logit));
    }
}

// ---------------- launch ----------------------------------------------------
extern "C" void kernel_launch(void* const* d_in, const int* in_sizes, int n_in,
                              void* d_out, int out_size)
{
    const float* x    = (const float*)d_in[0];
    const int*   dom  = (const int*)  d_in[1];
    const float* W1   = (const float*)d_in[2];
    const float* b1   = (const float*)d_in[3];
    const float* W2   = (const float*)d_in[4];
    const float* b2   = (const float*)d_in[5];
    const float* TW1  = (const float*)d_in[6];
    const float* Tb1  = (const float*)d_in[7];
    const float* TW2  = (const float*)d_in[8];
    const float* Tb2  = (const float*)d_in[9];
    const float* TWo  = (const float*)d_in[10];
    const float* Tbo  = (const float*)d_in[11];
    float* out = (float*)d_out;

    void *p;
    cudaGetSymbolAddress(&p, g_xb);   bf16* xb   = (bf16*)p;
    cudaGetSymbolAddress(&p, g_w1t);  bf16* w1t  = (bf16*)p;
    cudaGetSymbolAddress(&p, g_w2t);  bf16* w2t  = (bf16*)p;
    cudaGetSymbolAddress(&p, g_h1);   bf16* h1   = (bf16*)p;
    cudaGetSymbolAddress(&p, g_h2);   bf16* h2   = (bf16*)p;

    const int GEMM_SMEM = (2*128*72 + 2*128*72) * (int)sizeof(bf16);  // 73728
    cudaFuncSetAttribute(gemm_bf16_kernel<true>,  cudaFuncAttributeMaxDynamicSharedMemorySize, GEMM_SMEM);
    cudaFuncSetAttribute(gemm_bf16_kernel<false>, cudaFuncAttributeMaxDynamicSharedMemorySize, GEMM_SMEM);
    cudaFuncSetAttribute(tower_kernel, cudaFuncAttributeMaxDynamicSharedMemorySize, TW_SMEM);

    // 1) mega prep: scatter (fixed-stride buckets) + x convert + transposes
    prep_kernel<<<PREP_BLOCKS, 256>>>(dom, (const float4*)x, W1, W2, TW1, TW2);

    // 2) bottom MLP (GEMM1 carries the cursor->counts fixup)
    gemm_bf16_kernel<true><<<dim3(B_/128, H1_/128), 256, GEMM_SMEM>>>(
        xb, w1t, b1, h1, B_, H1_, FIN_);
    gemm_bf16_kernel<false><<<dim3(B_/128, H2_/128), 256, GEMM_SMEM>>>(
        h1, w2t, b2, h2, B_, H2_, H1_);

    // 3) fused towers: compact grid, 3-stage single-sync pipelines
    tower_kernel<<<TW_GRID, 256, TW_SMEM>>>(Tb1, Tb2, TWo, Tbo, out);
}